// round 14
// baseline (speedup 1.0000x reference)
#include <cuda_runtime.h>
#include <math.h>

// ---------------------------------------------------------------------------
// RotatedIoULoss — separable Green's-theorem clipping, MUFU-minimized.
// 2 adjacent boxes per thread (float2 loads, no smem staging).
//
// MUFU budget per box: 4 (two __sincosf) + 2 (paired edge reciprocals:
// rcp(dx*dy) -> 1/dx,1/dy via multiplies) + 0.5 (iou rcp paired across the
// thread's two boxes) + 1 (__logf) = 7.5, down from 11.
// Degenerate edges (exactly axis-parallel) make the paired rcp produce
// inf/NaN which resolves through fminf/fmaxf/__saturatef to collapsed
// zero-contribution windows — never NaN in the result.
// ---------------------------------------------------------------------------

#define IOU_EPS 1e-6f
#define BLOCK 128
#define MAXB  8192

__device__ float g_partial[MAXB];
__device__ unsigned int g_count = 0;   // reset by last block each launch

__device__ __forceinline__ float clampab(float v, float h) {
    return fminf(fmaxf(v, -h), h);
}

// returns (intersection_area, union_denominator)
__device__ __forceinline__ float2 box_inter(
    float px, float py, float pw, float ph, float pa,
    float qx, float qy, float qw, float qh, float qa) {

    // frame change into box2's local axes
    float cb, sb; __sincosf(qa, &sb, &cb);
    float dxc = px - qx, dyc = py - qy;
    float ox =  dxc * cb + dyc * sb;
    float oy = -dxc * sb + dyc * cb;
    float cr, sr; __sincosf(pa - qa, &sr, &cr);

    float hw = 0.5f * qw, hh = 0.5f * qh;
    float hx = 0.5f * pw, hy = 0.5f * ph;

    float ux = hx * cr,  uy = hx * sr;
    float wx = -hy * sr, wy = hy * cr;

    // corners (CCW)
    float v0x = ox + ux + wx, v0y = oy + uy + wy;
    float v1x = ox - ux + wx, v1y = oy - uy + wy;
    float v2x = ox - ux - wx, v2y = oy - uy - wy;
    float v3x = ox + ux - wx, v3y = oy + uy - wy;

    // edge dirs: A = v3->v0 = 2w, B = v0->v1 = -2u (C=-A, D=-B)
    float dAx = 2.f * wx, dAy = 2.f * wy;
    float dBx = -2.f * ux, dBy = -2.f * uy;
    // paired reciprocals: one RCP per edge-direction pair
    float rA = __fdividef(1.f, dAx * dAy);
    float rB = __fdividef(1.f, dBx * dBy);
    float iAx = dAy * rA, iAy = dAx * rA;
    float iBx = dBy * rB, iBy = dBx * rB;

    float area2 = 0.f;

#define EDGE(axv, ayv, dx_, dy_, ix_, iy_) do {                        \
        float ta = (-hw - (axv)) * (ix_);                              \
        float tb = ( hw - (axv)) * (ix_);                              \
        float tc = (-hh - (ayv)) * (iy_);                              \
        float td = ( hh - (ayv)) * (iy_);                              \
        float a_ = __saturatef(fminf(tc, td));                         \
        float b_ = __saturatef(fmaxf(tc, td));                         \
        float t1 = fminf(ta, tb), t2 = fmaxf(ta, tb);                  \
        float c1 = fminf(fmaxf(t1, a_), b_);                           \
        float c2 = fminf(fmaxf(t2, a_), b_);                           \
        float Xa = clampab(fmaf(a_, (dx_), (axv)), hw);                \
        float X1 = clampab(fmaf(c1, (dx_), (axv)), hw);                \
        float X2 = clampab(fmaf(c2, (dx_), (axv)), hw);                \
        float Xb = clampab(fmaf(b_, (dx_), (axv)), hw);                \
        float e = Xa * (c1 - a_);                                      \
        e = fmaf(X1, c2 - a_, e);                                      \
        e = fmaf(X2, b_ - c1, e);                                      \
        e = fmaf(Xb, b_ - c2, e);                                      \
        area2 = fmaf((dy_), e, area2);                                 \
    } while (0)

    EDGE(v3x, v3y,  dAx,  dAy,  iAx,  iAy);
    EDGE(v0x, v0y,  dBx,  dBy,  iBx,  iBy);
    EDGE(v1x, v1y, -dAx, -dAy, -iAx, -iAy);
    EDGE(v2x, v2y, -dBx, -dBy, -iBx, -iBy);
#undef EDGE

    float inter = 0.5f * fabsf(area2);

    // conservative separation: certain-disjoint -> exact zero (predicated)
    float radx = fabsf(ux) + fabsf(wx);
    float rady = fabsf(uy) + fabsf(wy);
    bool sep = (fabsf(ox) > hw + radx) || (fabsf(oy) > hh + rady);
    inter = sep ? 0.f : inter;

    float a1 = pw * ph, a2 = qw * qh;
    return make_float2(inter, a1 + a2 - inter);
}

__global__ void __launch_bounds__(BLOCK, 8)
rl_main(const float* __restrict__ pred,
        const float* __restrict__ target,
        const float* __restrict__ weight,
        float* __restrict__ out,
        int n, int nb, float inv_n) {
    int Tid = blockIdx.x * BLOCK + threadIdx.x;   // pair index
    int i0 = 2 * Tid;

    // benign defaults: inter=pi (any), denom -> iou=1, w=0 -> 0 loss
    float p0x = 0.f, p0y = 0.f, p0w = 1.f, p0h = 1.f, p0a = 0.f;
    float p1x = 0.f, p1y = 0.f, p1w = 1.f, p1h = 1.f, p1a = 0.f;
    float q0x = 0.f, q0y = 0.f, q0w = 1.f, q0h = 1.f, q0a = 0.f;
    float q1x = 0.f, q1y = 0.f, q1w = 1.f, q1h = 1.f, q1a = 0.f;
    float w0 = 0.f, w1 = 0.f;

    if (i0 + 1 < n) {
        const float2* p2 = (const float2*)(pred)   + (size_t)Tid * 5;
        const float2* t2 = (const float2*)(target) + (size_t)Tid * 5;
        float2 a0 = p2[0], a1 = p2[1], a2 = p2[2], a3 = p2[3], a4 = p2[4];
        float2 b0 = t2[0], b1 = t2[1], b2 = t2[2], b3 = t2[3], b4 = t2[4];
        float2 ww = ((const float2*)weight)[Tid];
        p0x = a0.x; p0y = a0.y; p0w = a1.x; p0h = a1.y; p0a = a2.x;
        p1x = a2.y; p1y = a3.x; p1w = a3.y; p1h = a4.x; p1a = a4.y;
        q0x = b0.x; q0y = b0.y; q0w = b1.x; q0h = b1.y; q0a = b2.x;
        q1x = b2.y; q1y = b3.x; q1w = b3.y; q1h = b4.x; q1a = b4.y;
        w0 = ww.x; w1 = ww.y;
    } else if (i0 < n) {
        const float* P = pred + (size_t)i0 * 5;
        const float* T = target + (size_t)i0 * 5;
        p0x = P[0]; p0y = P[1]; p0w = P[2]; p0h = P[3]; p0a = P[4];
        q0x = T[0]; q0y = T[1]; q0w = T[2]; q0h = T[3]; q0a = T[4];
        w0 = weight[i0];
    }

    // two independent chains
    float2 r0 = box_inter(p0x, p0y, p0w, p0h, p0a, q0x, q0y, q0w, q0h, q0a);
    float2 r1 = box_inter(p1x, p1y, p1w, p1h, p1a, q1x, q1y, q1w, q1h, q1a);

    // paired iou division: one RCP for both boxes (denoms strictly > 0)
    float rr = __fdividef(1.f, r0.y * r1.y);
    float iou0 = fmaxf(r0.x * (r1.y * rr), IOU_EPS);
    float iou1 = fmaxf(r1.x * (r0.y * rr), IOU_EPS);
    float loss = fmaf(-__logf(iou0), w0, -__logf(iou1) * w1);

    // ---- block reduction -> per-block partial ----
    unsigned mask = 0xFFFFFFFFu;
#pragma unroll
    for (int o = 16; o > 0; o >>= 1)
        loss += __shfl_down_sync(mask, loss, o);

    __shared__ float ws[BLOCK / 32];
    int lane = threadIdx.x & 31;
    int wid = threadIdx.x >> 5;
    if (lane == 0) ws[wid] = loss;
    __syncthreads();
    __shared__ bool is_last;
    if (threadIdx.x == 0) {
        float v = 0.f;
#pragma unroll
        for (int w = 0; w < BLOCK / 32; w++) v += ws[w];
        g_partial[blockIdx.x] = v;
        __threadfence();
        unsigned prev = atomicAdd(&g_count, 1u);
        is_last = (prev == (unsigned)(nb - 1));
    }
    __syncthreads();

    // ---- last block: final reduction (deterministic) ----
    if (is_last) {
        double s = 0.0;
        for (int j = threadIdx.x; j < nb; j += BLOCK)
            s += (double)g_partial[j];
#pragma unroll
        for (int o = 16; o > 0; o >>= 1)
            s += __shfl_down_sync(mask, s, o);
        __shared__ double ds[BLOCK / 32];
        if (lane == 0) ds[wid] = s;
        __syncthreads();
        if (threadIdx.x == 0) {
            double v = 0.0;
#pragma unroll
            for (int w = 0; w < BLOCK / 32; w++) v += ds[w];
            out[0] = (float)(v * (double)inv_n);
            g_count = 0;  // reset for next graph replay
        }
    }
}

extern "C" void kernel_launch(void* const* d_in, const int* in_sizes, int n_in,
                              void* d_out, int out_size) {
    const float* pred   = (const float*)d_in[0];
    const float* target = (const float*)d_in[1];
    const float* weight = (const float*)d_in[2];
    float* out = (float*)d_out;
    int n = in_sizes[2];

    int pairs = (n + 1) / 2;
    int grid = (pairs + BLOCK - 1) / BLOCK;
    if (grid > MAXB) grid = MAXB;  // n = 1e6 -> 3907 blocks
    rl_main<<<grid, BLOCK>>>(pred, target, weight, out, n, grid,
                             1.0f / (float)n);
}